// round 1
// baseline (speedup 1.0000x reference)
#include <cuda_runtime.h>

// Fused 2-layer GCN on a chain graph.
// Per block: 126 output nodes. Halo-2 on x, halo-1 on h1.
//   xagg = A(x)         (tridiagonal normalized aggregation, 128 rows)
//   h1   = relu(xagg @ W1 + b1)          [128 x 128]
//   z    = A(h1)        (in-place, 126 valid rows)
//   out  = z @ W2 + b2                   [126 x 64]
// dinv: 1/sqrt(3) interior, 1/sqrt(2) at nodes 0 and N-1, 0 out of range
// (out-of-range handled purely by zero coefficients).

#define NTHREADS 256
#define TILE     126

__global__ __launch_bounds__(NTHREADS, 1)
void gcn_fused(const float* __restrict__ x,
               const float* __restrict__ W1, const float* __restrict__ b1,
               const float* __restrict__ W2, const float* __restrict__ b2,
               float* __restrict__ out, int N)
{
    extern __shared__ float smem[];
    float* sW1 = smem;                   // [64][128]   8192
    float* sW2 = sW1 + 64 * 128;         // [128][64]   8192
    float* sXT = sW2 + 128 * 64;         // [64][128]   xaggT[k][j]
    float* sH  = sXT + 64 * 128;         // [128][128]  h1T[c][j], then zT
    float* sXs = sH  + 128 * 128;        // [130][65]   staged x rows (padded stride)
    float* sdv = sXs + 130 * 65;         // [131] dinv for nodes base-2 .. base+128
    float* sb1 = sdv + 132;              // [128]
    float* sb2 = sb1 + 128;              // [64]

    const int tid = threadIdx.x;
    const long long base = (long long)blockIdx.x * TILE;

    // ---- stage weights / biases / dinv / x halo tile ----
    for (int i = tid; i < 64 * 128; i += NTHREADS) sW1[i] = W1[i];
    for (int i = tid; i < 128 * 64; i += NTHREADS) sW2[i] = W2[i];
    if (tid < 128) sb1[tid] = b1[tid];
    if (tid < 64)  sb2[tid] = b2[tid];
    if (tid < 131) {
        long long node = base - 2 + tid;
        float v = 0.0f;
        if (node >= 0 && node < (long long)N)
            v = (node == 0 || node == (long long)N - 1)
                ? 0.70710678118654752f   // 1/sqrt(2)
                : 0.57735026918962576f;  // 1/sqrt(3)
        sdv[tid] = v;
    }
    for (int e = tid; e < 130 * 64; e += NTHREADS) {
        int t = e >> 6, k = e & 63;
        long long node = base - 2 + t;
        sXs[t * 65 + k] = (node >= 0 && node < (long long)N)
                          ? x[node * 64 + k] : 0.0f;
    }
    __syncthreads();

    // ---- xaggT[k][j], row j = node base-1+j, j in [0,128) ----
    for (int e = tid; e < 128 * 64; e += NTHREADS) {
        int j = e & 127, k = e >> 7;
        float v = sdv[j + 1] * (sdv[j]     * sXs[ j      * 65 + k]
                              + sdv[j + 1] * sXs[(j + 1) * 65 + k]
                              + sdv[j + 2] * sXs[(j + 2) * 65 + k]);
        sXT[k * 128 + j] = v;
    }
    __syncthreads();

    // ---- matmul1: h1T[c][j] = relu( sum_k xaggT[k][j] * W1[k][c] + b1[c] )
    // 128x128 output, 8x8 register tiles, 256 threads = 16x16 tiles.
    {
        const int rt = tid & 15, ct = tid >> 4;
        const int r0 = rt * 8, c0 = ct * 8;
        float acc[8][8];
        #pragma unroll
        for (int i = 0; i < 8; i++)
            #pragma unroll
            for (int j = 0; j < 8; j++) acc[i][j] = 0.0f;

        #pragma unroll 4
        for (int k = 0; k < 64; k++) {
            float4 a0 = *(const float4*)(sXT + k * 128 + r0);
            float4 a1 = *(const float4*)(sXT + k * 128 + r0 + 4);
            float4 w0 = *(const float4*)(sW1 + k * 128 + c0);
            float4 w1 = *(const float4*)(sW1 + k * 128 + c0 + 4);
            float av[8] = {a0.x, a0.y, a0.z, a0.w, a1.x, a1.y, a1.z, a1.w};
            float wv[8] = {w0.x, w0.y, w0.z, w0.w, w1.x, w1.y, w1.z, w1.w};
            #pragma unroll
            for (int i = 0; i < 8; i++)
                #pragma unroll
                for (int j = 0; j < 8; j++)
                    acc[i][j] = fmaf(av[i], wv[j], acc[i][j]);
        }
        #pragma unroll
        for (int j = 0; j < 8; j++) {
            float bb = sb1[c0 + j];
            float4 v0, v1;
            v0.x = fmaxf(acc[0][j] + bb, 0.0f);
            v0.y = fmaxf(acc[1][j] + bb, 0.0f);
            v0.z = fmaxf(acc[2][j] + bb, 0.0f);
            v0.w = fmaxf(acc[3][j] + bb, 0.0f);
            v1.x = fmaxf(acc[4][j] + bb, 0.0f);
            v1.y = fmaxf(acc[5][j] + bb, 0.0f);
            v1.z = fmaxf(acc[6][j] + bb, 0.0f);
            v1.w = fmaxf(acc[7][j] + bb, 0.0f);
            *(float4*)(sH + (c0 + j) * 128 + r0)     = v0;
            *(float4*)(sH + (c0 + j) * 128 + r0 + 4) = v1;
        }
    }
    __syncthreads();

    // ---- z = A(h1) in place on sH.  z row r (r<126) = node base+r, uses
    // h1 rows r..r+2.  Two phases (r<64, r>=64) with register staging so all
    // reads of a region complete before any write to it.
    {
        float zr[32];
        int c = 0;
        for (int e = tid; e < 8192; e += NTHREADS, c++) {
            int r = e & 63, k = e >> 6;
            zr[c] = sdv[r + 2] * (sdv[r + 1] * sH[k * 128 + r]
                                + sdv[r + 2] * sH[k * 128 + r + 1]
                                + sdv[r + 3] * sH[k * 128 + r + 2]);
        }
        __syncthreads();
        c = 0;
        for (int e = tid; e < 8192; e += NTHREADS, c++) {
            int r = e & 63, k = e >> 6;
            sH[k * 128 + r] = zr[c];          // writes rows 0..63 only
        }
        // phase B reads rows 64..127 (disjoint from phase-A writes)
        c = 0;
        for (int e = tid; e < 8192; e += NTHREADS, c++) {
            int r = 64 + (e & 63), k = e >> 6;
            zr[c] = (r < TILE)
                  ? sdv[r + 2] * (sdv[r + 1] * sH[k * 128 + r]
                                + sdv[r + 2] * sH[k * 128 + r + 1]
                                + sdv[r + 3] * sH[k * 128 + r + 2])
                  : 0.0f;
        }
        __syncthreads();
        c = 0;
        for (int e = tid; e < 8192; e += NTHREADS, c++) {
            int r = 64 + (e & 63), k = e >> 6;
            if (r < TILE) sH[k * 128 + r] = zr[c];
        }
    }
    __syncthreads();

    // ---- matmul2: out[r][c] = sum_k zT[k][r] * W2[k][c] + b2[c]
    // 128(126 valid) x 64 output, 4x8 tiles, 256 threads = 32x8 tiles.
    {
        const int rt = tid & 31, ct = tid >> 5;
        const int r0 = rt * 4, c0 = ct * 8;
        float acc[4][8];
        #pragma unroll
        for (int i = 0; i < 4; i++)
            #pragma unroll
            for (int j = 0; j < 8; j++) acc[i][j] = 0.0f;

        #pragma unroll 4
        for (int k = 0; k < 128; k++) {
            float4 a  = *(const float4*)(sH  + k * 128 + r0);
            float4 w0 = *(const float4*)(sW2 + k * 64 + c0);
            float4 w1 = *(const float4*)(sW2 + k * 64 + c0 + 4);
            float av[4] = {a.x, a.y, a.z, a.w};
            float wv[8] = {w0.x, w0.y, w0.z, w0.w, w1.x, w1.y, w1.z, w1.w};
            #pragma unroll
            for (int i = 0; i < 4; i++)
                #pragma unroll
                for (int j = 0; j < 8; j++)
                    acc[i][j] = fmaf(av[i], wv[j], acc[i][j]);
        }
        #pragma unroll
        for (int i = 0; i < 4; i++) {
            int r = r0 + i;
            long long node = base + r;
            if (r < TILE && node < (long long)N) {
                float4 o0, o1;
                o0.x = acc[i][0] + sb2[c0 + 0];
                o0.y = acc[i][1] + sb2[c0 + 1];
                o0.z = acc[i][2] + sb2[c0 + 2];
                o0.w = acc[i][3] + sb2[c0 + 3];
                o1.x = acc[i][4] + sb2[c0 + 4];
                o1.y = acc[i][5] + sb2[c0 + 5];
                o1.z = acc[i][6] + sb2[c0 + 6];
                o1.w = acc[i][7] + sb2[c0 + 7];
                *(float4*)(out + node * 64 + c0)     = o0;
                *(float4*)(out + node * 64 + c0 + 4) = o1;
            }
        }
    }
}

extern "C" void kernel_launch(void* const* d_in, const int* in_sizes, int n_in,
                              void* d_out, int out_size)
{
    // metadata order: x (f32), edge_index (int64, unused: fixed chain),
    //                 W1, b1, W2, b2 (f32)
    const float* x  = (const float*)d_in[0];
    const float* W1 = (const float*)d_in[2];
    const float* b1 = (const float*)d_in[3];
    const float* W2 = (const float*)d_in[4];
    const float* b2 = (const float*)d_in[5];
    float* out = (float*)d_out;

    int N = in_sizes[0] / 64;
    int nblocks = (N + TILE - 1) / TILE;

    size_t smem_bytes = (size_t)(64 * 128 + 128 * 64 + 64 * 128 + 128 * 128 +
                                 130 * 65 + 132 + 128 + 64) * sizeof(float);
    cudaFuncSetAttribute(gcn_fused,
                         cudaFuncAttributeMaxDynamicSharedMemorySize,
                         (int)smem_bytes);
    gcn_fused<<<nblocks, NTHREADS, smem_bytes>>>(x, W1, b1, W2, b2, out, N);
}

// round 3
// speedup vs baseline: 1.1299x; 1.1299x over previous
#include <cuda_runtime.h>
#include <cuda_bf16.h>
#include <mma.h>
#include <cstdint>

using namespace nvcuda;

// Fused 2-layer GCN (chain graph), wmma bf16 3-term split GEMMs (HMMA path;
// tcgen05 unavailable: harness emits compute_103 PTX without the 'a' feature).
//
// Per CTA tile of 126 output nodes (rows padded to 128):
//   xagg = tridiag(x)  fp32 -> split bf16 hi/lo A1[128][64]
//   C1 = 3-term wmma (M128 N128 K64)  -> sH fp32 (raw accum)
//   z  = tridiag(relu(C1+b1)) -> split A2[128][128]
//   C2 = 3-term wmma (M128 N64 K128)  -> out = C2 + b2

#define NTHREADS 256
#define TILE     126

// ---- smem layout (bytes) ----
#define LDA1 72      // bf16 elems per row, A1 [128][64]
#define LDB1 136     // B1 [64][128]
#define LDA2 136     // A2 [128][128]
#define LDB2 72      // B2 [128][64]
#define LDH  132     // fp32, sH [128][128]
#define LDXS 68      // fp32, sXs [130][64]
#define LDO  68      // fp32, sOut [128][64]

#define OFF_R0   0                    // sXs (35360) / A2h+A2l (69632)
#define OFF_A2H  0
#define OFF_A2L  34816
#define OFF_A1H  69632
#define OFF_A1L  88064
#define OFF_R2   106496               // B1h/l (34816) then B2h/l (36864)
#define OFF_B1H  106496
#define OFF_B1L  123904
#define OFF_B2H  106496
#define OFF_B2L  124928
#define OFF_SH   143360               // 128*132*4 = 67584 ; sOut overlays
#define OFF_SDV  210944               // 132 floats
#define OFF_SB1  211472               // 128 floats
#define OFF_SB2  211984               // 64 floats
#define SMEM_BYTES 212240

__device__ __forceinline__ void split_bf16(float v, __nv_bfloat16& hi,
                                           __nv_bfloat16& lo) {
    hi = __float2bfloat16_rn(v);
    lo = __float2bfloat16_rn(v - __bfloat162float(hi));
}

__global__ __launch_bounds__(NTHREADS, 1)
void gcn_wmma(const float* __restrict__ x,
              const float* __restrict__ W1, const float* __restrict__ b1,
              const float* __restrict__ W2, const float* __restrict__ b2,
              float* __restrict__ out, int N)
{
    extern __shared__ char smem[];
    const int tid = threadIdx.x, wid = tid >> 5;
    const long long base = (long long)blockIdx.x * TILE;

    float* sdv  = (float*)(smem + OFF_SDV);
    float* sb1v = (float*)(smem + OFF_SB1);
    float* sb2v = (float*)(smem + OFF_SB2);
    float* sXs  = (float*)(smem + OFF_R0);
    float* sH   = (float*)(smem + OFF_SH);
    float* sOut = (float*)(smem + OFF_SH);
    __nv_bfloat16* A1h = (__nv_bfloat16*)(smem + OFF_A1H);
    __nv_bfloat16* A1l = (__nv_bfloat16*)(smem + OFF_A1L);
    __nv_bfloat16* B1h = (__nv_bfloat16*)(smem + OFF_B1H);
    __nv_bfloat16* B1l = (__nv_bfloat16*)(smem + OFF_B1L);
    __nv_bfloat16* A2h = (__nv_bfloat16*)(smem + OFF_A2H);
    __nv_bfloat16* A2l = (__nv_bfloat16*)(smem + OFF_A2L);
    __nv_bfloat16* B2h = (__nv_bfloat16*)(smem + OFF_B2H);
    __nv_bfloat16* B2l = (__nv_bfloat16*)(smem + OFF_B2L);

    // ---------- phase 1: stage dinv/biases/x/W1-split ----------
    if (tid < 131) {
        long long node = base - 2 + tid;
        float v = 0.0f;
        if (node >= 0 && node < (long long)N)
            v = (node == 0 || node == (long long)N - 1)
                ? 0.70710678118654752f : 0.57735026918962576f;
        sdv[tid] = v;
    }
    if (tid < 128) sb1v[tid] = b1[tid];
    if (tid < 64)  sb2v[tid] = b2[tid];

    for (int e = tid; e < 64 * 128; e += NTHREADS) {    // W1[k][c]
        int k = e >> 7, c = e & 127;
        __nv_bfloat16 hi, lo;
        split_bf16(W1[e], hi, lo);
        B1h[k * LDB1 + c] = hi;
        B1l[k * LDB1 + c] = lo;
    }
    for (int e = tid; e < 130 * 16; e += NTHREADS) {    // x halo rows
        int t = e >> 4, q = e & 15;
        long long node = base - 2 + t;
        float4 v = make_float4(0.f, 0.f, 0.f, 0.f);
        if (node >= 0 && node < (long long)N)
            v = *(const float4*)(x + node * 64 + q * 4);
        *(float4*)&sXs[t * LDXS + q * 4] = v;
    }
    __syncthreads();

    // ---------- phase 2: xagg tridiag + split -> A1 ----------
    for (int e = tid; e < 128 * 64; e += NTHREADS) {
        int j = e >> 6, k = e & 63;
        float d0 = sdv[j], d1 = sdv[j + 1], d2 = sdv[j + 2];
        float a = d1 * (d0 * sXs[j * LDXS + k] +
                        d1 * sXs[(j + 1) * LDXS + k] +
                        d2 * sXs[(j + 2) * LDXS + k]);
        __nv_bfloat16 hi, lo;
        split_bf16(a, hi, lo);
        A1h[j * LDA1 + k] = hi;
        A1l[j * LDA1 + k] = lo;
    }
    __syncthreads();

    // ---------- phase 3: MMA1  C1[128][128] = A1 @ B1 (3-term) ----------
    {
        const int row0 = wid * 16;
        wmma::fragment<wmma::matrix_a, 16, 16, 16, __nv_bfloat16, wmma::row_major> ah, al;
        wmma::fragment<wmma::matrix_b, 16, 16, 16, __nv_bfloat16, wmma::row_major> bh, bl;
        wmma::fragment<wmma::accumulator, 16, 16, 16, float> acc[8];
        #pragma unroll
        for (int j = 0; j < 8; j++) wmma::fill_fragment(acc[j], 0.0f);

        #pragma unroll
        for (int k = 0; k < 4; k++) {
            wmma::load_matrix_sync(ah, A1h + row0 * LDA1 + k * 16, LDA1);
            wmma::load_matrix_sync(al, A1l + row0 * LDA1 + k * 16, LDA1);
            #pragma unroll
            for (int j = 0; j < 8; j++) {
                wmma::load_matrix_sync(bh, B1h + (k * 16) * LDB1 + j * 16, LDB1);
                wmma::load_matrix_sync(bl, B1l + (k * 16) * LDB1 + j * 16, LDB1);
                wmma::mma_sync(acc[j], ah, bh, acc[j]);
                wmma::mma_sync(acc[j], ah, bl, acc[j]);
                wmma::mma_sync(acc[j], al, bh, acc[j]);
            }
        }
        #pragma unroll
        for (int j = 0; j < 8; j++)
            wmma::store_matrix_sync(sH + row0 * LDH + j * 16, acc[j], LDH,
                                    wmma::mem_row_major);
    }
    __syncthreads();

    // ---------- phase 4: stage W2 split (over B1) + stencil2 -> A2 ----------
    for (int e = tid; e < 128 * 64; e += NTHREADS) {    // W2[k][c]
        int k = e >> 6, c = e & 63;
        __nv_bfloat16 hi, lo;
        split_bf16(W2[e], hi, lo);
        B2h[k * LDB2 + c] = hi;
        B2l[k * LDB2 + c] = lo;
    }
    for (int e = tid; e < 128 * 128; e += NTHREADS) {
        int r = e >> 7, k = e & 127;
        float z = 0.0f;
        if (r < TILE) {
            float bb = sb1v[k];
            float h0 = fmaxf(sH[ r      * LDH + k] + bb, 0.0f);
            float h1 = fmaxf(sH[(r + 1) * LDH + k] + bb, 0.0f);
            float h2 = fmaxf(sH[(r + 2) * LDH + k] + bb, 0.0f);
            z = sdv[r + 2] * (sdv[r + 1] * h0 + sdv[r + 2] * h1 +
                              sdv[r + 3] * h2);
        }
        __nv_bfloat16 hi, lo;
        split_bf16(z, hi, lo);
        A2h[r * LDA2 + k] = hi;
        A2l[r * LDA2 + k] = lo;
    }
    __syncthreads();

    // ---------- phase 5: MMA2  C2[128][64] = A2 @ B2 (3-term) ----------
    {
        const int row0 = wid * 16;
        wmma::fragment<wmma::matrix_a, 16, 16, 16, __nv_bfloat16, wmma::row_major> ah, al;
        wmma::fragment<wmma::matrix_b, 16, 16, 16, __nv_bfloat16, wmma::row_major> bh, bl;
        wmma::fragment<wmma::accumulator, 16, 16, 16, float> acc[4];
        #pragma unroll
        for (int j = 0; j < 4; j++) wmma::fill_fragment(acc[j], 0.0f);

        #pragma unroll
        for (int k = 0; k < 8; k++) {
            wmma::load_matrix_sync(ah, A2h + row0 * LDA2 + k * 16, LDA2);
            wmma::load_matrix_sync(al, A2l + row0 * LDA2 + k * 16, LDA2);
            #pragma unroll
            for (int j = 0; j < 4; j++) {
                wmma::load_matrix_sync(bh, B2h + (k * 16) * LDB2 + j * 16, LDB2);
                wmma::load_matrix_sync(bl, B2l + (k * 16) * LDB2 + j * 16, LDB2);
                wmma::mma_sync(acc[j], ah, bh, acc[j]);
                wmma::mma_sync(acc[j], ah, bl, acc[j]);
                wmma::mma_sync(acc[j], al, bh, acc[j]);
            }
        }
        // sOut overlays sH; stencil2 reads of sH completed at last barrier.
        #pragma unroll
        for (int j = 0; j < 4; j++)
            wmma::store_matrix_sync(sOut + row0 * LDO + j * 16, acc[j], LDO,
                                    wmma::mem_row_major);
    }
    __syncthreads();

    // ---------- phase 6: out = C2 + b2, coalesced ----------
    for (int e = tid; e < TILE * 16; e += NTHREADS) {
        int r = e >> 4, q = e & 15;
        long long node = base + r;
        if (node < (long long)N) {
            float4 v = *(float4*)&sOut[r * LDO + q * 4];
            v.x += sb2v[q * 4 + 0];
            v.y += sb2v[q * 4 + 1];
            v.z += sb2v[q * 4 + 2];
            v.w += sb2v[q * 4 + 3];
            *(float4*)(out + node * 64 + q * 4) = v;
        }
    }
}

extern "C" void kernel_launch(void* const* d_in, const int* in_sizes, int n_in,
                              void* d_out, int out_size)
{
    const float* x  = (const float*)d_in[0];
    const float* W1 = (const float*)d_in[2];
    const float* b1 = (const float*)d_in[3];
    const float* W2 = (const float*)d_in[4];
    const float* b2 = (const float*)d_in[5];
    float* out = (float*)d_out;

    int N = in_sizes[0] / 64;
    int nblocks = (N + TILE - 1) / TILE;

    cudaFuncSetAttribute(gcn_wmma,
                         cudaFuncAttributeMaxDynamicSharedMemorySize,
                         SMEM_BYTES);
    gcn_wmma<<<nblocks, NTHREADS, SMEM_BYTES>>>(x, W1, b1, W2, b2, out, N);
}

// round 4
// speedup vs baseline: 1.6172x; 1.4312x over previous
#include <cuda_runtime.h>
#include <cuda_fp16.h>
#include <mma.h>
#include <cstdint>

using namespace nvcuda;

// Fused 2-layer GCN (chain graph), wmma fp16 3-term split, 2 CTAs/SM.
// Per CTA: 64 output nodes. MMA1 rows j=0..79 (h node = base-1+j, j<=65 used).
//   A1 = split(tridiag(x))          [80 x 64]
//   sH = A1 @ W1split               [80 x 128] fp32 raw accum
//   per k-chunk (64): A2c = split(tridiag(relu(sH+b1)))[.., kc:kc+64]
//                     acc += A2c @ W2split[kc:kc+64,:]   (regs persist)
//   out = acc + b2
// B1 region reused for B2 after MMA1. sXs/sH/sOut share a region.

#define NTHREADS 256
#define OUT_TILE 64
#define MROWS    80

#define LDA 72      // fp16 elems: A1 [80][64], A2c [64][64]
#define LDB1 136    // B1 [64][128]
#define LDB2 72     // B2 [128][64]
#define LDH 130     // fp32 sH [80][128]
#define LDX 68      // fp32 sXs [69][64]
#define LDO 68      // fp32 sOut [64][64]

#define OFF_A1H 0            // 80*72*2 = 11520
#define OFF_A1L 11520
#define OFF_A2H 0            // 64*72*2 = 9216 (overlays A1, dead after MMA1)
#define OFF_A2L 9216
#define OFF_B   23040        // B1h/B1l: 64*136*2 = 17408 each
#define OFF_B1H OFF_B
#define OFF_B1L (OFF_B + 17408)
#define OFF_B2H OFF_B        // B2h/B2l: 128*72*2 = 18432 each (after MMA1)
#define OFF_B2L (OFF_B + 18432)
#define OFF_SH  59904        // sH 80*130*4 = 41600 ; sXs/sOut overlay
#define OFF_SDV 101504       // 72 floats
#define OFF_SB1 101792       // 128 floats
#define OFF_SB2 102304       // 64 floats
#define SMEM_BYTES 102560

__device__ __forceinline__ void split_h(float v, __half& hi, __half& lo) {
    hi = __float2half_rn(v);
    lo = __float2half_rn(v - __half2float(hi));
}

__global__ __launch_bounds__(NTHREADS, 2)
void gcn_wmma2(const float* __restrict__ x,
               const float* __restrict__ W1, const float* __restrict__ b1,
               const float* __restrict__ W2, const float* __restrict__ b2,
               float* __restrict__ out, int N)
{
    extern __shared__ char smem[];
    const int tid = threadIdx.x, wid = tid >> 5;
    const long long base = (long long)blockIdx.x * OUT_TILE;

    float* sdv  = (float*)(smem + OFF_SDV);   // idx t -> node base-2+t, t<69
    float* sb1v = (float*)(smem + OFF_SB1);
    float* sb2v = (float*)(smem + OFF_SB2);
    float* sXs  = (float*)(smem + OFF_SH);    // [69][LDX]
    float* sH   = (float*)(smem + OFF_SH);    // [80][LDH]
    float* sOut = (float*)(smem + OFF_SH);    // [64][LDO]
    __half* A1h = (__half*)(smem + OFF_A1H);
    __half* A1l = (__half*)(smem + OFF_A1L);
    __half* A2h = (__half*)(smem + OFF_A2H);
    __half* A2l = (__half*)(smem + OFF_A2L);
    __half* B1h = (__half*)(smem + OFF_B1H);
    __half* B1l = (__half*)(smem + OFF_B1L);
    __half* B2h = (__half*)(smem + OFF_B2H);
    __half* B2l = (__half*)(smem + OFF_B2L);

    // ---------- P1: stage dinv / biases / W1 split / x ----------
    if (tid < 72) {
        long long node = base - 2 + tid;
        float v = 0.0f;
        if (tid < 69 && node >= 0 && node < (long long)N)
            v = (node == 0 || node == (long long)N - 1)
                ? 0.70710678118654752f : 0.57735026918962576f;
        sdv[tid] = v;
    }
    if (tid < 128) sb1v[tid] = b1[tid];
    if (tid < 64)  sb2v[tid] = b2[tid];

    for (int e = tid; e < 64 * 128; e += NTHREADS) {   // W1[k][c]
        int k = e >> 7, c = e & 127;
        __half hi, lo;
        split_h(W1[e], hi, lo);
        B1h[k * LDB1 + c] = hi;
        B1l[k * LDB1 + c] = lo;
    }
    for (int e = tid; e < 69 * 16; e += NTHREADS) {    // x rows base-2..base+66
        int t = e / 16, q = e & 15;
        long long node = base - 2 + t;
        float4 v = make_float4(0.f, 0.f, 0.f, 0.f);
        if (node >= 0 && node < (long long)N)
            v = *(const float4*)(x + node * 64 + q * 4);
        *(float4*)&sXs[t * LDX + q * 4] = v;
    }
    __syncthreads();

    // ---------- P2: stencil1 + split -> A1 [80][64] ----------
    // row j -> h node m = base-1+j ; x stage rows j, j+1, j+2 ; valid j<=66
    for (int e = tid; e < MROWS * 64; e += NTHREADS) {
        int j = e >> 6, k = e & 63;
        float a = 0.0f;
        if (j <= 66) {
            float d0 = sdv[j], d1 = sdv[j + 1], d2 = sdv[j + 2];
            a = d1 * (d0 * sXs[j * LDX + k] +
                      d1 * sXs[(j + 1) * LDX + k] +
                      d2 * sXs[(j + 2) * LDX + k]);
        }
        __half hi, lo;
        split_h(a, hi, lo);
        A1h[j * LDA + k] = hi;
        A1l[j * LDA + k] = lo;
    }
    __syncthreads();

    // ---------- P3: MMA1  sH[80][128] = A1 @ B1 (3-term) ----------
    // warp w: colslab w (16 cols), rowslabs 0..4
    {
        wmma::fragment<wmma::matrix_a, 16, 16, 16, __half, wmma::row_major> ah, al;
        wmma::fragment<wmma::matrix_b, 16, 16, 16, __half, wmma::row_major> bh, bl;
        wmma::fragment<wmma::accumulator, 16, 16, 16, float> acc[5];
        #pragma unroll
        for (int r = 0; r < 5; r++) wmma::fill_fragment(acc[r], 0.0f);

        #pragma unroll
        for (int k = 0; k < 4; k++) {
            wmma::load_matrix_sync(bh, B1h + (k * 16) * LDB1 + wid * 16, LDB1);
            wmma::load_matrix_sync(bl, B1l + (k * 16) * LDB1 + wid * 16, LDB1);
            #pragma unroll
            for (int r = 0; r < 5; r++) {
                wmma::load_matrix_sync(ah, A1h + (r * 16) * LDA + k * 16, LDA);
                wmma::load_matrix_sync(al, A1l + (r * 16) * LDA + k * 16, LDA);
                wmma::mma_sync(acc[r], ah, bh, acc[r]);
                wmma::mma_sync(acc[r], ah, bl, acc[r]);
                wmma::mma_sync(acc[r], al, bh, acc[r]);
            }
        }
        __syncthreads();   // sXs (overlaid by sH) dead
        #pragma unroll
        for (int r = 0; r < 5; r++)
            wmma::store_matrix_sync(sH + (r * 16) * LDH + wid * 16, acc[r],
                                    LDH, wmma::mem_row_major);
    }
    __syncthreads();       // sH ready; B1 dead

    // ---------- P4: W2 split -> B2 (over B1) + K-chunked stencil2/MMA2 ----
    for (int e = tid; e < 128 * 64; e += NTHREADS) {   // W2[k][c]
        int k = e >> 6, c = e & 63;
        __half hi, lo;
        split_h(W2[e], hi, lo);
        B2h[k * LDB2 + c] = hi;
        B2l[k * LDB2 + c] = lo;
    }

    // MMA2 accumulators persist across the two K-chunks.
    // warp w: colslab c = w&3, rowslabs rs0=(w>>2)*2, rs0+1
    wmma::fragment<wmma::accumulator, 16, 16, 16, float> acc2[2];
    wmma::fill_fragment(acc2[0], 0.0f);
    wmma::fill_fragment(acc2[1], 0.0f);
    const int c2 = (wid & 3) * 16, rs0 = (wid >> 2) * 2;

    #pragma unroll
    for (int kc = 0; kc < 128; kc += 64) {
        // stencil2 chunk: z[r][k], r=0..63, k=kc..kc+63
        // node n = base+r ; h rows r, r+1, r+2 ; dinv idx r+1, r+2, r+3
        for (int e = tid; e < 64 * 64; e += NTHREADS) {
            int r = e >> 6, k = kc + (e & 63);
            float bb = sb1v[k];
            float h0 = fmaxf(sH[ r      * LDH + k] + bb, 0.0f);
            float h1 = fmaxf(sH[(r + 1) * LDH + k] + bb, 0.0f);
            float h2 = fmaxf(sH[(r + 2) * LDH + k] + bb, 0.0f);
            float z = sdv[r + 2] * (sdv[r + 1] * h0 + sdv[r + 2] * h1 +
                                    sdv[r + 3] * h2);
            __half hi, lo;
            split_h(z, hi, lo);
            A2h[r * LDA + (e & 63)] = hi;
            A2l[r * LDA + (e & 63)] = lo;
        }
        __syncthreads();   // A2c + (first iter) B2 ready

        {
            wmma::fragment<wmma::matrix_a, 16, 16, 16, __half, wmma::row_major> ah, al;
            wmma::fragment<wmma::matrix_b, 16, 16, 16, __half, wmma::row_major> bh, bl;
            #pragma unroll
            for (int kk = 0; kk < 4; kk++) {
                wmma::load_matrix_sync(bh, B2h + (kc + kk * 16) * LDB2 + c2, LDB2);
                wmma::load_matrix_sync(bl, B2l + (kc + kk * 16) * LDB2 + c2, LDB2);
                #pragma unroll
                for (int r = 0; r < 2; r++) {
                    wmma::load_matrix_sync(ah, A2h + ((rs0 + r) * 16) * LDA + kk * 16, LDA);
                    wmma::load_matrix_sync(al, A2l + ((rs0 + r) * 16) * LDA + kk * 16, LDA);
                    wmma::mma_sync(acc2[r], ah, bh, acc2[r]);
                    wmma::mma_sync(acc2[r], ah, bl, acc2[r]);
                    wmma::mma_sync(acc2[r], al, bh, acc2[r]);
                }
            }
        }
        __syncthreads();   // A2c reads done before next chunk overwrites
    }

    // ---------- P5: store acc2 -> sOut (overlays sH) -> global ----------
    wmma::store_matrix_sync(sOut + (rs0 * 16) * LDO + c2, acc2[0], LDO,
                            wmma::mem_row_major);
    wmma::store_matrix_sync(sOut + ((rs0 + 1) * 16) * LDO + c2, acc2[1], LDO,
                            wmma::mem_row_major);
    __syncthreads();

    for (int e = tid; e < OUT_TILE * 16; e += NTHREADS) {
        int r = e >> 4, q = e & 15;
        long long node = base + r;
        if (node < (long long)N) {
            float4 v = *(float4*)&sOut[r * LDO + q * 4];
            v.x += sb2v[q * 4 + 0];
            v.y += sb2v[q * 4 + 1];
            v.z += sb2v[q * 4 + 2];
            v.w += sb2v[q * 4 + 3];
            *(float4*)(out + node * 64 + q * 4) = v;
        }
    }
}

extern "C" void kernel_launch(void* const* d_in, const int* in_sizes, int n_in,
                              void* d_out, int out_size)
{
    const float* x  = (const float*)d_in[0];
    const float* W1 = (const float*)d_in[2];
    const float* b1 = (const float*)d_in[3];
    const float* W2 = (const float*)d_in[4];
    const float* b2 = (const float*)d_in[5];
    float* out = (float*)d_out;

    int N = in_sizes[0] / 64;
    int nblocks = (N + OUT_TILE - 1) / OUT_TILE;

    cudaFuncSetAttribute(gcn_wmma2,
                         cudaFuncAttributeMaxDynamicSharedMemorySize,
                         SMEM_BYTES);
    gcn_wmma2<<<nblocks, NTHREADS, SMEM_BYTES>>>(x, W1, b1, W2, b2, out, N);
}